// round 2
// baseline (speedup 1.0000x reference)
#include <cuda_runtime.h>
#include <math_constants.h>

#define MAX_B 8192
__device__ float g_partials[MAX_B];
__device__ unsigned int g_done_count;   // zero-init; auto-wraps to 0 each launch

#define DEPTH_PARAM 0.5f
#define LENGTH_PENALTY 1.5f

struct ArgMax { float v; int i; };

__device__ __forceinline__ void am_update(ArgMax& a, float v, int i) {
    // strict >: first occurrence wins within a chain (indices increase per chain)
    if (v > a.v) { a.v = v; a.i = i; }
}

__device__ __forceinline__ void am_combine(ArgMax& a, float v, int i) {
    if (v > a.v || (v == a.v && i < a.i)) { a.v = v; a.i = i; }
}

__device__ __forceinline__ ArgMax warp_reduce(ArgMax a) {
    #pragma unroll
    for (int off = 16; off; off >>= 1) {
        float ov = __shfl_down_sync(0xffffffffu, a.v, off);
        int   oi = __shfl_down_sync(0xffffffffu, a.i, off);
        am_combine(a, ov, oi);
    }
    return a;
}

// One block per batch row: dual argmax + tree-walk epilogue + fused final reduce
// (last block to finish does the deterministic fixed-order sum).
__global__ __launch_bounds__(256, 8)
void hloss_fused_kernel(const float* __restrict__ y_pred,
                        const float* __restrict__ y_true,
                        const float* __restrict__ class_weights,
                        const int*   __restrict__ path_ids,
                        const int*   __restrict__ path_len,
                        const int*   __restrict__ sib_start,
                        const int*   __restrict__ sib_size,
                        float* __restrict__ out,
                        int C, int D, int B)
{
    const int b   = blockIdx.x;
    const int tid = threadIdx.x;
    const int nth = blockDim.x;

    const float* __restrict__ rp = y_pred + (size_t)b * C;
    const float* __restrict__ rt = y_true + (size_t)b * C;

    // 4 independent accumulator chains per input stream (ILP: no serial
    // dependence between the 4 lanes of a float4).
    ArgMax ap[4], at[4];
    #pragma unroll
    for (int k = 0; k < 4; k++) {
        ap[k].v = -CUDART_INF_F; ap[k].i = 0;
        at[k].v = -CUDART_INF_F; at[k].i = 0;
    }

    const int C4 = C >> 2;
    const float4* __restrict__ rp4 = (const float4*)rp;
    const float4* __restrict__ rt4 = (const float4*)rt;

    for (int i = tid; i < C4; i += nth) {
        const int base = i << 2;
        float4 vp = rp4[i];
        float4 vt = rt4[i];
        am_update(ap[0], vp.x, base + 0);
        am_update(ap[1], vp.y, base + 1);
        am_update(ap[2], vp.z, base + 2);
        am_update(ap[3], vp.w, base + 3);
        am_update(at[0], vt.x, base + 0);
        am_update(at[1], vt.y, base + 1);
        am_update(at[2], vt.z, base + 2);
        am_update(at[3], vt.w, base + 3);
    }
    // scalar tail (C=2728 is divisible by 4; kept for robustness)
    for (int i = (C4 << 2) + tid; i < C; i += nth) {
        am_update(ap[0], rp[i], i);
        am_update(at[0], rt[i], i);
    }

    // merge the 4 chains (index-aware: lowest index wins ties)
    ArgMax apf = ap[0], atf = at[0];
    #pragma unroll
    for (int k = 1; k < 4; k++) {
        am_combine(apf, ap[k].v, ap[k].i);
        am_combine(atf, at[k].v, at[k].i);
    }

    __shared__ float s_pv[8]; __shared__ int s_pi[8];
    __shared__ float s_tv[8]; __shared__ int s_ti[8];
    __shared__ unsigned int s_ticket;

    apf = warp_reduce(apf);
    atf = warp_reduce(atf);
    const int lane = tid & 31;
    const int wid  = tid >> 5;
    if (lane == 0) { s_pv[wid] = apf.v; s_pi[wid] = apf.i;
                     s_tv[wid] = atf.v; s_ti[wid] = atf.i; }
    __syncthreads();

    if (tid == 0) {
        const int nwarps = nth >> 5;
        ArgMax fp; fp.v = s_pv[0]; fp.i = s_pi[0];
        ArgMax ft; ft.v = s_tv[0]; ft.i = s_ti[0];
        for (int w = 1; w < nwarps; w++) {
            am_combine(fp, s_pv[w], s_pi[w]);
            am_combine(ft, s_tv[w], s_ti[w]);
        }
        const int pt = fp.i;              // pred_top
        const int tt = ft.i;              // true_top

        const int lp = path_len[pt];
        const int lt = path_len[tt];
        const int diff = abs(lp - lt);

        float total = 0.0f;
        if (diff != 0) {
            const int lmin = (lp < lt) ? lp : lt;
            float local = 0.0f;
            for (int l = 0; l < lmin; l++) {
                const int st = sib_start[tt * D + l];
                const int sz = sib_size [tt * D + l];
                // lse over (y_pred * 0/1-mask): masked classes contribute exp(0)=1
                float s = (float)(C - sz);
                for (int j = 0; j < sz; j++) s += expf(rp[st + j]);
                const float lse = logf(s);
                const float tl  = rp[path_ids[tt * D + l]];
                const float h   = (float)(lt - l - 1);
                local += expf(-DEPTH_PARAM * h) * (lse - tl);
            }
            total = local * (LENGTH_PENALTY * (float)diff) * class_weights[tt];
        }
        g_partials[b] = total;

        // publish partial, take a ticket; atomicInc wraps to 0 after the last
        // block, so the counter self-resets every launch (graph-replay safe).
        __threadfence();
        s_ticket = atomicInc(&g_done_count, (unsigned)(gridDim.x - 1));
    }
    __syncthreads();

    if (s_ticket == (unsigned)(gridDim.x - 1)) {
        // Last block: deterministic fixed-order final reduction.
        __shared__ float sm[256];
        float s = 0.0f;
        for (int i = tid; i < B; i += nth) s += g_partials[i];
        sm[tid] = s;
        __syncthreads();
        #pragma unroll
        for (int k = 128; k > 0; k >>= 1) {
            if (tid < k) sm[tid] += sm[tid + k];
            __syncthreads();
        }
        if (tid == 0) out[0] = sm[0] / (float)B;
    }
}

extern "C" void kernel_launch(void* const* d_in, const int* in_sizes, int n_in,
                              void* d_out, int out_size)
{
    const float* y_pred        = (const float*)d_in[0];
    const float* y_true        = (const float*)d_in[1];
    const float* class_weights = (const float*)d_in[2];
    const int*   path_ids      = (const int*)  d_in[3];
    const int*   path_len      = (const int*)  d_in[4];
    const int*   sib_start     = (const int*)  d_in[5];
    const int*   sib_size      = (const int*)  d_in[6];

    const int C = in_sizes[2];              // class_weights has C elements
    const int B = in_sizes[0] / C;          // y_pred is [B, C]
    const int D = in_sizes[3] / C;          // path_ids is [C, D]

    hloss_fused_kernel<<<B, 256>>>(y_pred, y_true, class_weights,
                                   path_ids, path_len, sib_start, sib_size,
                                   (float*)d_out, C, D, B);
}